// round 6
// baseline (speedup 1.0000x reference)
#include <cuda_runtime.h>
#include <math.h>

#define NN 10000
#define EE 160000
#define FF 32
#define NCH 9
#define TNODES 16

// ---------------- device scratch (static, no allocations) ----------------
__device__ float g_x[NN * NCH * FF];     // node features
__device__ float g_y[NN * NCH * FF];     // message accumulator
__device__ float g_geo[EE * 25];         // per edge: sph[9], rad[16]

struct CGc { float v[729]; };

// ---------------- host: analytic Gaunt coefficients -----------------------
static double dfact_h(int n) { double v = 1.0; for (int k = n; k >= 2; k -= 2) v *= (double)k; return v; }

static void compute_cg(CGc* cg) {
    const double c0 = 0.28209479177387814, c1 = 0.4886025119029199,
                 c2a = 1.0925484305920792, c2b = 0.31539156525252005,
                 c2c = 0.5462742152960396;
    double tc[9][2]; int te[9][2][3]; int nt[9];
    for (int i = 0; i < 9; i++) { nt[i] = 1; tc[i][1] = 0.0; te[i][1][0] = te[i][1][1] = te[i][1][2] = 0; }
    tc[0][0] = c0;      te[0][0][0]=0; te[0][0][1]=0; te[0][0][2]=0;
    tc[1][0] = c1;      te[1][0][0]=0; te[1][0][1]=1; te[1][0][2]=0;
    tc[2][0] = c1;      te[2][0][0]=0; te[2][0][1]=0; te[2][0][2]=1;
    tc[3][0] = c1;      te[3][0][0]=1; te[3][0][1]=0; te[3][0][2]=0;
    tc[4][0] = c2a;     te[4][0][0]=1; te[4][0][1]=1; te[4][0][2]=0;
    tc[5][0] = c2a;     te[5][0][0]=0; te[5][0][1]=1; te[5][0][2]=1;
    tc[6][0] = 3.0*c2b; te[6][0][0]=0; te[6][0][1]=0; te[6][0][2]=2;
    tc[6][1] = -c2b;    te[6][1][0]=0; te[6][1][1]=0; te[6][1][2]=0; nt[6] = 2;
    tc[7][0] = c2a;     te[7][0][0]=1; te[7][0][1]=0; te[7][0][2]=1;
    tc[8][0] = c2c;     te[8][0][0]=2; te[8][0][1]=0; te[8][0][2]=0;
    tc[8][1] = -c2c;    te[8][1][0]=0; te[8][1][1]=2; te[8][1][2]=0; nt[8] = 2;

    const double fourpi = 12.566370614359172464;
    for (int a = 0; a < 9; a++)
      for (int b = 0; b < 9; b++)
        for (int c = 0; c < 9; c++) {
            double g = 0.0;
            for (int i = 0; i < nt[a]; i++)
              for (int j = 0; j < nt[b]; j++)
                for (int k = 0; k < nt[c]; k++) {
                    int p = te[a][i][0] + te[b][j][0] + te[c][k][0];
                    int q = te[a][i][1] + te[b][j][1] + te[c][k][1];
                    int r = te[a][i][2] + te[b][j][2] + te[c][k][2];
                    if ((p | q | r) & 1) continue;
                    double I = fourpi * dfact_h(p - 1) * dfact_h(q - 1) * dfact_h(r - 1)
                               / dfact_h(p + q + r + 1);
                    g += tc[a][i] * tc[b][j] * tc[c][k] * I;
                }
            if (fabs(g) < 1e-6) g = 0.0;
            cg->v[(a * 9 + b) * 9 + c] = (float)g;
        }
}

// ---------------- kernels -------------------------------------------------

__global__ void k_init(const int* __restrict__ z, const float* __restrict__ embed) {
    int idx = blockIdx.x * blockDim.x + threadIdx.x;
    if (idx >= NN * NCH * FF) return;
    g_y[idx] = 0.0f;
    int f = idx & 31;
    int c = (idx >> 5) % 9;
    int n = idx / (NCH * FF);
    g_x[idx] = (c == 0) ? embed[z[n] * FF + f] : 0.0f;
}

__global__ void k_geom(const float* __restrict__ pos, const int* __restrict__ dst,
                       const int* __restrict__ src) {
    int e = blockIdx.x * blockDim.x + threadIdx.x;
    if (e >= EE) return;
    int s = src[e], d = dst[e];
    float dx = pos[s * 3 + 0] - pos[d * 3 + 0];
    float dy = pos[s * 3 + 1] - pos[d * 3 + 1];
    float dz = pos[s * 3 + 2] - pos[d * 3 + 2];
    float r = sqrtf(dx * dx + dy * dy + dz * dz + 1e-12f);
    float inv = 1.0f / r;
    float x = dx * inv, y = dy * inv, z = dz * inv;
    const float c0 = 0.28209479177387814f, c1 = 0.4886025119029199f,
                c2a = 1.0925484305920792f, c2b = 0.31539156525252005f,
                c2c = 0.5462742152960396f;
    float* g = &g_geo[(size_t)e * 25];
    g[0] = c0;
    g[1] = c1 * y;  g[2] = c1 * z;  g[3] = c1 * x;
    g[4] = c2a * x * y; g[5] = c2a * y * z;
    g[6] = c2b * (3.0f * z * z - 1.0f);
    g[7] = c2a * x * z; g[8] = c2c * (x * x - y * y);

    float u1 = 1.0f / (1.0f + r);
    float om = 1.0f - u1;
    float A[16], B[16];
    A[0] = 1.0f;
    #pragma unroll
    for (int k = 1; k < 16; k++) A[k] = A[k - 1] * u1;
    B[15] = 1.0f;
    #pragma unroll
    for (int k = 14; k >= 0; k--) B[k] = B[k + 1] * om;
    float t = r * 0.25f;
    float fc = 0.0f;
    if (t < 1.0f) {
        float den = 1.0f - t * t;
        fc = expf(-t * t / den);
    }
    const float binom[16] = {1.f,15.f,105.f,455.f,1365.f,3003.f,5005.f,6435.f,
                             6435.f,5005.f,3003.f,1365.f,455.f,105.f,15.f,1.f};
    #pragma unroll
    for (int k = 0; k < 16; k++) g[9 + k] = binom[k] * A[k] * B[k] * fc;
}

__global__ void __launch_bounds__(256, 2)
k_edge(const int* __restrict__ dst, const int* __restrict__ src,
       const float* __restrict__ Wb_i, CGc cg) {
    const int lane = threadIdx.x & 31;
    const int warp = (blockIdx.x * blockDim.x + threadIdx.x) >> 5;
    const int nwarp = (gridDim.x * blockDim.x) >> 5;

    float w0[16], w1[16], w2[16];
    #pragma unroll
    for (int n = 0; n < 16; n++) {
        w0[n] = Wb_i[(0 * 16 + n) * 32 + lane];
        w1[n] = Wb_i[(1 * 16 + n) * 32 + lane];
        w2[n] = Wb_i[(2 * 16 + n) * 32 + lane];
    }

    for (int e = warp; e < EE; e += nwarp) {
        int s = src[e], d = dst[e];
        float gv = g_geo[(size_t)e * 25 + (lane < 25 ? lane : 0)];

        float R0 = 0.f, R1 = 0.f, R2 = 0.f;
        #pragma unroll
        for (int n = 0; n < 16; n++) {
            float rn = __shfl_sync(0xffffffffu, gv, 9 + n);
            R0 = fmaf(rn, w0[n], R0);
            R1 = fmaf(rn, w1[n], R1);
            R2 = fmaf(rn, w2[n], R2);
        }
        float bfv[9];
        #pragma unroll
        for (int b = 0; b < 9; b++) {
            float sb = __shfl_sync(0xffffffffu, gv, b);
            bfv[b] = sb * (b == 0 ? R0 : (b < 4 ? R1 : R2));
        }
        float xa[9];
        const float* xp = &g_x[(size_t)s * 288 + lane];
        #pragma unroll
        for (int a = 0; a < 9; a++) xa[a] = xp[a * 32];

        float msg[9];
        #pragma unroll
        for (int c = 0; c < 9; c++) msg[c] = 0.f;

#define GV(A,B,C) cg.v[(A)*81 + (B)*9 + (C)]
#define TPA(A,B,C) msg[C] = fmaf(GV(A,B,C), xa[A] * bfv[B], msg[C]);
#define TPS(A,B,C) msg[C] = fmaf(GV(A,B,C), fmaf(xa[A], bfv[B], xa[B] * bfv[A]), msg[C]);
        TPA(0,0,0) TPA(1,1,0) TPA(2,2,0) TPA(3,3,0) TPA(4,4,0)
        TPA(5,5,0) TPA(6,6,0) TPA(7,7,0) TPA(8,8,0)
        TPS(0,6,0) TPS(0,8,0) TPS(6,8,0)
        TPA(0,0,6) TPA(1,1,6) TPA(2,2,6) TPA(3,3,6) TPA(4,4,6)
        TPA(5,5,6) TPA(6,6,6) TPA(7,7,6) TPA(8,8,6)
        TPS(0,6,6) TPS(0,8,6) TPS(6,8,6)
        TPA(0,0,8) TPA(1,1,8) TPA(2,2,8) TPA(3,3,8) TPA(4,4,8)
        TPA(5,5,8) TPA(6,6,8) TPA(7,7,8) TPA(8,8,8)
        TPS(0,6,8) TPS(0,8,8) TPS(6,8,8)
        TPS(0,1,1) TPS(6,1,1) TPS(8,1,1) TPS(3,4,1) TPS(2,5,1)
        TPS(0,2,2) TPS(6,2,2) TPS(8,2,2) TPS(3,7,2) TPS(1,5,2)
        TPS(0,3,3) TPS(6,3,3) TPS(8,3,3) TPS(1,4,3) TPS(2,7,3)
        TPS(0,4,4) TPS(6,4,4) TPS(8,4,4) TPS(1,3,4) TPS(5,7,4)
        TPS(0,5,5) TPS(6,5,5) TPS(8,5,5) TPS(1,2,5) TPS(4,7,5)
        TPS(0,7,7) TPS(6,7,7) TPS(8,7,7) TPS(2,3,7) TPS(4,5,7)
#undef GV
#undef TPA
#undef TPS

        float* yp = &g_y[(size_t)d * 288 + lane];
        #pragma unroll
        for (int c = 0; c < 9; c++) atomicAdd(&yp[c * 32], msg[c]);
    }
}

// node kernel: warp-per-channel, weight columns in registers, smem float4
// broadcast for activations. Tile of TNODES nodes per block.
//   y = x + agg; h = silu(W1 y + b1); x += W2 h + b2.  Also re-zeroes g_y.
__global__ void __launch_bounds__(288, 2)
k_node(const float* __restrict__ W1, const float* __restrict__ b1,
       const float* __restrict__ W2, const float* __restrict__ b2) {
    __shared__ float ybuf[TNODES * 288];
    __shared__ float hbuf[TNODES * 288];
    const int t = threadIdx.x;
    const int warp = t >> 5, lane = t & 31;
    const int c = warp;                      // channel 0..8
    const int DEGc[9] = {0, 1, 1, 1, 2, 2, 2, 2, 2};
    const int d = DEGc[c];

    // weight columns for my output feature g=lane (registers)
    float w1c[32], w2c[32];
    #pragma unroll
    for (int f = 0; f < 32; f++) {
        w1c[f] = W1[(d * 32 + f) * 32 + lane];
        w2c[f] = W2[(d * 32 + f) * 32 + lane];
    }
    const float b1g = (c == 0) ? b1[lane] : 0.0f;
    const float b2g = (c == 0) ? b2[lane] : 0.0f;

    for (int n0 = blockIdx.x * TNODES; n0 < NN; n0 += gridDim.x * TNODES) {
        const int base = n0 * 288;
        // phase 1: stage y = x + agg, re-zero agg (coalesced)
        #pragma unroll
        for (int i = 0; i < TNODES; i++) {
            int off = i * 288 + t;
            ybuf[off] = g_x[base + off] + g_y[base + off];
            g_y[base + off] = 0.0f;
        }
        __syncthreads();
        // phase 2a: layer 1 + silu for my channel, all tile nodes
        #pragma unroll
        for (int i = 0; i < TNODES; i++) {
            const float4* y4 = (const float4*)&ybuf[i * 288 + c * 32];
            float a0 = b1g, a1 = 0.f, a2 = 0.f, a3 = 0.f;
            #pragma unroll
            for (int j = 0; j < 8; j++) {
                float4 q = y4[j];
                a0 = fmaf(q.x, w1c[4 * j + 0], a0);
                a1 = fmaf(q.y, w1c[4 * j + 1], a1);
                a2 = fmaf(q.z, w1c[4 * j + 2], a2);
                a3 = fmaf(q.w, w1c[4 * j + 3], a3);
            }
            float acc = (a0 + a1) + (a2 + a3);
            hbuf[i * 288 + c * 32 + lane] = acc / (1.0f + __expf(-acc));
        }
        __syncthreads();
        // phase 2b: layer 2 + residual into g_x
        #pragma unroll
        for (int i = 0; i < TNODES; i++) {
            const float4* h4 = (const float4*)&hbuf[i * 288 + c * 32];
            float a0 = b2g, a1 = 0.f, a2 = 0.f, a3 = 0.f;
            #pragma unroll
            for (int j = 0; j < 8; j++) {
                float4 q = h4[j];
                a0 = fmaf(q.x, w2c[4 * j + 0], a0);
                a1 = fmaf(q.y, w2c[4 * j + 1], a1);
                a2 = fmaf(q.z, w2c[4 * j + 2], a2);
                a3 = fmaf(q.w, w2c[4 * j + 3], a3);
            }
            int idx = base + i * 288 + c * 32 + lane;
            g_x[idx] += (a0 + a1) + (a2 + a3);
        }
        __syncthreads();   // before next tile overwrites ybuf
    }
}

// output head: mono (N,4) then dip (N,3,4)
__global__ void __launch_bounds__(256)
k_out(const int* __restrict__ z, const float* __restrict__ pos,
      const float* __restrict__ Wt00, const float* __restrict__ Wt11,
      const float* __restrict__ Wmono, const float* __restrict__ ebias,
      float* __restrict__ out) {
    int lane = threadIdx.x & 31;
    int n = (blockIdx.x * blockDim.x + threadIdx.x) >> 5;
    if (n >= NN) return;

    float x0 = g_x[n * 288 + lane];
    float tj[4];
    #pragma unroll
    for (int j = 0; j < 4; j++) {
        float p = x0 * Wt00[lane * 4 + j];
        #pragma unroll
        for (int o = 16; o > 0; o >>= 1) p += __shfl_xor_sync(0xffffffffu, p, o);
        tj[j] = p;
    }
    if (lane < 4) {
        float m = 0.0f;
        #pragma unroll
        for (int k = 0; k < 4; k++) m = fmaf(tj[k], Wmono[k * 4 + lane], m);
        m += ebias[z[n]];
        out[n * 4 + lane] = m;
    }
    #pragma unroll
    for (int c = 0; c < 3; c++) {
        float xc = g_x[n * 288 + (1 + c) * 32 + lane];
        #pragma unroll
        for (int j = 0; j < 4; j++) {
            float p = xc * Wt11[lane * 4 + j];
            #pragma unroll
            for (int o = 16; o > 0; o >>= 1) p += __shfl_xor_sync(0xffffffffu, p, o);
            if (lane == 0) {
                float sv = p / (1.0f + expf(-p));
                sv = fminf(fmaxf(sv, -0.3f), 0.3f);
                out[NN * 4 + (n * 3 + c) * 4 + j] = sv + pos[n * 3 + c];
            }
        }
    }
}

// ---------------- launch --------------------------------------------------
extern "C" void kernel_launch(void* const* d_in, const int* in_sizes, int n_in,
                              void* d_out, int out_size) {
    const int*   z     = (const int*)d_in[0];
    const float* pos   = (const float*)d_in[1];
    const int*   dst   = (const int*)d_in[2];
    const int*   src   = (const int*)d_in[3];
    const float* embed = (const float*)d_in[4];
    const float* Wb    = (const float*)d_in[5];
    const float* W1    = (const float*)d_in[6];
    const float* b1    = (const float*)d_in[7];
    const float* W2    = (const float*)d_in[8];
    const float* b2    = (const float*)d_in[9];
    const float* Wt00  = (const float*)d_in[10];
    const float* Wt11  = (const float*)d_in[11];
    const float* Wmono = (const float*)d_in[12];
    const float* ebias = (const float*)d_in[13];
    float* out = (float*)d_out;

    CGc cg;
    compute_cg(&cg);

    k_init<<<(NN * NCH * FF + 255) / 256, 256>>>(z, embed);
    k_geom<<<(EE + 255) / 256, 256>>>(pos, dst, src);
    for (int i = 0; i < 3; i++) {
        k_edge<<<2048, 256>>>(dst, src, Wb + i * 3 * 16 * 32, cg);
        k_node<<<625, 288>>>(W1 + i * 3 * 32 * 32, b1 + i * 32,
                             W2 + i * 3 * 32 * 32, b2 + i * 32);
    }
    k_out<<<(NN * 32 + 255) / 256, 256>>>(z, pos, Wt00, Wt11, Wmono, ebias, out);
}